// round 7
// baseline (speedup 1.0000x reference)
#include <cuda_runtime.h>
#include <math.h>

#define NN 4096
#define F_IN 128
#define HH 4
#define FO 64
#define D2 256
#define VV 16
#define H1 96
#define H2 32

// ---------------- scratch (device globals; no allocs allowed) ----------------
__device__ float g_p[NN * D2];       // x @ Wp1
__device__ float g_skip[NN * D2];    // x @ Wskip1
__device__ float g_out1[NN * D2];    // elu(attn-out + skip + bias1)
__device__ float g_p2[NN * D2];      // out1 @ Wp2
__device__ float g_ssrc[HH * NN];
__device__ float g_stgt[HH * NN];
__device__ float g_E1s[HH * NN];
__device__ float g_E2s[HH * NN];
__device__ float g_E1t[HH * NN];
__device__ float g_E2t[HH * NN];
__device__ float g_ss[NN];
__device__ float g_st[NN];
__device__ float g_h1[NN * H1];      // msw @ W1 (accumulated via atomics)

// ---------------- fused dual SGEMM: g_p = x@Wp1, g_skip = x@Wsk ----------------
// M=4096, K=128, N=256. Block = 256 threads, 64x64 C tile (two outputs).
__global__ void __launch_bounds__(256) xgemm_dual(const float* __restrict__ x,
                                                  const float* __restrict__ Wp1,
                                                  const float* __restrict__ Wsk) {
    __shared__ float As[16][64];
    __shared__ float B1s[16][64];
    __shared__ float B2s[16][64];
    int t = threadIdx.x;
    int tx = t & 15, ty = t >> 4;
    int m0 = blockIdx.y * 64, n0 = blockIdx.x * 64;
    float acc1[4][4] = {};
    float acc2[4][4] = {};
    for (int k0 = 0; k0 < F_IN; k0 += 16) {
#pragma unroll
        for (int i = 0; i < 4; i++) {
            int lin = t + i * 256;
            int m = lin >> 4, k = lin & 15;
            As[k][m] = x[(size_t)(m0 + m) * F_IN + k0 + k];
        }
#pragma unroll
        for (int i = 0; i < 4; i++) {
            int lin = t + i * 256;
            int k = lin >> 6, n = lin & 63;
            B1s[k][n] = Wp1[(size_t)(k0 + k) * D2 + n0 + n];
            B2s[k][n] = Wsk[(size_t)(k0 + k) * D2 + n0 + n];
        }
        __syncthreads();
#pragma unroll
        for (int k = 0; k < 16; k++) {
            float a[4], b1[4], b2[4];
#pragma unroll
            for (int r = 0; r < 4; r++) a[r] = As[k][ty * 4 + r];
#pragma unroll
            for (int c = 0; c < 4; c++) { b1[c] = B1s[k][tx * 4 + c]; b2[c] = B2s[k][tx * 4 + c]; }
#pragma unroll
            for (int r = 0; r < 4; r++)
#pragma unroll
                for (int c = 0; c < 4; c++) {
                    acc1[r][c] = fmaf(a[r], b1[c], acc1[r][c]);
                    acc2[r][c] = fmaf(a[r], b2[c], acc2[r][c]);
                }
        }
        __syncthreads();
    }
#pragma unroll
    for (int r = 0; r < 4; r++)
#pragma unroll
        for (int c = 0; c < 4; c++) {
            size_t idx = (size_t)(m0 + ty * 4 + r) * D2 + n0 + tx * 4 + c;
            g_p[idx] = acc1[r][c];
            g_skip[idx] = acc2[r][c];
        }
}

// ---------------- SGEMM: g_p2 = g_out1 @ Wp2 (4096x256 @ 256x256) ----------------
__global__ void __launch_bounds__(256) p2gemm(const float* __restrict__ Wp2) {
    __shared__ float As[16][64];
    __shared__ float Bs[16][64];
    int t = threadIdx.x;
    int tx = t & 15, ty = t >> 4;
    int m0 = blockIdx.y * 64, n0 = blockIdx.x * 64;
    float acc[4][4] = {};
    for (int k0 = 0; k0 < D2; k0 += 16) {
#pragma unroll
        for (int i = 0; i < 4; i++) {
            int lin = t + i * 256;
            int m = lin >> 4, k = lin & 15;
            As[k][m] = g_out1[(size_t)(m0 + m) * D2 + k0 + k];
        }
#pragma unroll
        for (int i = 0; i < 4; i++) {
            int lin = t + i * 256;
            int k = lin >> 6, n = lin & 63;
            Bs[k][n] = Wp2[(size_t)(k0 + k) * D2 + n0 + n];
        }
        __syncthreads();
#pragma unroll
        for (int k = 0; k < 16; k++) {
            float a[4], b[4];
#pragma unroll
            for (int r = 0; r < 4; r++) a[r] = As[k][ty * 4 + r];
#pragma unroll
            for (int c = 0; c < 4; c++) b[c] = Bs[k][tx * 4 + c];
#pragma unroll
            for (int r = 0; r < 4; r++)
#pragma unroll
                for (int c = 0; c < 4; c++) acc[r][c] = fmaf(a[r], b[c], acc[r][c]);
        }
        __syncthreads();
    }
#pragma unroll
    for (int r = 0; r < 4; r++)
#pragma unroll
        for (int c = 0; c < 4; c++)
            g_p2[(size_t)(m0 + ty * 4 + r) * D2 + n0 + tx * 4 + c] = acc[r][c];
}

// ---------------- per-node GAT scores + exp factor tables ----------------
__global__ void node_scores(const float* __restrict__ a_src,
                            const float* __restrict__ a_tgt) {
    int t = blockIdx.x * blockDim.x + threadIdx.x;
    if (t >= NN * HH) return;
    int n = t >> 2, h = t & 3;
    const float* pr = g_p + (size_t)n * D2 + h * FO;
    float ss = 0.f, st = 0.f;
#pragma unroll 8
    for (int f = 0; f < FO; f++) {
        float pv = pr[f];
        ss = fmaf(pv, a_src[h * FO + f], ss);
        st = fmaf(pv, a_tgt[h * FO + f], st);
    }
    int idx = h * NN + n;
    g_ssrc[idx] = ss;
    g_stgt[idx] = st;
    g_E1s[idx] = expf(ss);
    g_E2s[idx] = expf(0.2f * ss);
    g_E1t[idx] = expf(st);
    g_E2t[idx] = expf(0.2f * st);
}

// ---------------- fused GAT attention (weights on the fly) ----------------
// out1[i,c] = elu( (sum_j w[h,i,j] * p[j,c]) / Z[h,i] + skip[i,c] + bias1[c] )
// w[h,i,j] = valid(i,j) ? ((ss_i+st_j > 0) ? E1s_i*E1t_j : E2s_i*E2t_j) : 0
// Block: 32 rows x 256 cols, 4 rows per warp; loops over j in chunks of 16.
__global__ void __launch_bounds__(256) attn_kernel(const float* __restrict__ sw,
                                                   const float* __restrict__ bias1) {
    __shared__ float Psh[16][256];
    __shared__ float Wt[32][16][4];                  // [i][j][h]
    __shared__ float ss_sh[4][32], E1s_sh[4][32], E2s_sh[4][32];
    __shared__ float st_sh[4][16], E1t_sh[4][16], E2t_sh[4][16];
    __shared__ float Zsh[32][4];

    int t = threadIdx.x;
    int i0 = blockIdx.x * 32;

    // per-row (i) constants: 4 heads x 32 rows = 128 entries
    if (t < 128) {
        int h = t >> 5, i = t & 31;
        int idx = h * NN + i0 + i;
        ss_sh[h][i] = g_ssrc[idx];
        E1s_sh[h][i] = g_E1s[idx];
        E2s_sh[h][i] = g_E2s[idx];
        Zsh[i][h] = 0.f;
    }

    // fma role: warp w owns rows r0..r0+3, lane owns cols c0..c0+7
    int w = t >> 5, tx = t & 31;
    int r0 = w * 4;
    int head = tx >> 3;
    int c0 = tx * 8;

    float zpart[2][4] = {};
    float acc[4][8] = {};

    for (int j0 = 0; j0 < NN; j0 += 16) {
        __syncthreads();
        if (t < 64) {
            int h = t >> 4, jj = t & 15;
            int idx = h * NN + j0 + jj;
            st_sh[h][jj] = g_stgt[idx];
            E1t_sh[h][jj] = g_E1t[idx];
            E2t_sh[h][jj] = g_E2t[idx];
        }
#pragma unroll
        for (int i = 0; i < 16; i++)
            Psh[i][t] = g_p[(size_t)(j0 + i) * D2 + t];
        __syncthreads();

        // weight-builder: 32x16 = 512 entries, 2 per thread
#pragma unroll
        for (int e = 0; e < 2; e++) {
            int lin = t + e * 256;
            int wi = lin >> 4, wj = lin & 15;
            float swv = sw[(size_t)(i0 + wi) * NN + j0 + wj];
            bool valid = swv > 0.f;
#pragma unroll
            for (int h = 0; h < 4; h++) {
                float tv = ss_sh[h][wi] + st_sh[h][wj];
                float wgt = 0.f;
                if (valid)
                    wgt = (tv > 0.f) ? E1s_sh[h][wi] * E1t_sh[h][wj]
                                     : E2s_sh[h][wi] * E2t_sh[h][wj];
                Wt[wi][wj][h] = wgt;
                zpart[e][h] += wgt;
            }
        }
        __syncthreads();

#pragma unroll
        for (int k = 0; k < 16; k++) {
            float wr[4];
#pragma unroll
            for (int r = 0; r < 4; r++) wr[r] = Wt[r0 + r][k][head];
            float4 pa = *(const float4*)&Psh[k][c0];
            float4 pb = *(const float4*)&Psh[k][c0 + 4];
            float pv[8] = {pa.x, pa.y, pa.z, pa.w, pb.x, pb.y, pb.z, pb.w};
#pragma unroll
            for (int r = 0; r < 4; r++)
#pragma unroll
                for (int c = 0; c < 8; c++)
                    acc[r][c] = fmaf(wr[r], pv[c], acc[r][c]);
        }
    }
    __syncthreads();
#pragma unroll
    for (int e = 0; e < 2; e++) {
        int wi = (t + e * 256) >> 4;
#pragma unroll
        for (int h = 0; h < 4; h++) atomicAdd(&Zsh[wi][h], zpart[e][h]);
    }
    __syncthreads();

#pragma unroll
    for (int r = 0; r < 4; r++) {
        int gi = i0 + r0 + r;
        float zinv = 1.f / Zsh[r0 + r][head];
#pragma unroll
        for (int c = 0; c < 8; c++) {
            int gc = c0 + c;
            float v = acc[r][c] * zinv + g_skip[(size_t)gi * D2 + gc] + bias1[gc];
            g_out1[(size_t)gi * D2 + gc] = (v > 0.f) ? v : expm1f(v);
        }
    }
}

// ---------------- GATW scores ----------------
__global__ void gatw_scores(const float* __restrict__ a_src2,
                            const float* __restrict__ a_tgt2) {
    int n = blockIdx.x * blockDim.x + threadIdx.x;
    if (n >= NN) return;
    float ss = 0.f, st = 0.f;
    const float* row = g_p2 + (size_t)n * D2;
#pragma unroll 8
    for (int c = 0; c < D2; c++) {
        float v = row[c];
        ss = fmaf(v, a_src2[c], ss);
        st = fmaf(v, a_tgt2[c], st);
    }
    g_ss[n] = ss;
    g_st[n] = st;
}

__global__ void zero_h1() {
    int t = blockIdx.x * blockDim.x + threadIdx.x;
    if (t < NN * H1) g_h1[t] = 0.f;
}

// ---------------- fused msw + (msw @ W1) with split-K atomics ----------------
// msw[i,j] = relu(ss[i]+st[j]) * sw[i,j]   (written to d_out)
// h1[i,c] += sum_j msw[i,j] * W1[j,c]
// Block tile: 32 rows x 96 cols. grid.x = j-split (8 x 512), grid.y = row blocks (128)
__global__ void __launch_bounds__(256) msw_h1(const float* __restrict__ sw,
                                              const float* __restrict__ W1,
                                              float* __restrict__ msw_out) {
    __shared__ float ss_sh[32];
    __shared__ float st_sh[16];
    __shared__ float W1t[16][96];
    __shared__ float mt[32][16];

    int t = threadIdx.x;
    int i0 = blockIdx.y * 32;
    int jbase = blockIdx.x * 512;
    if (t < 32) ss_sh[t] = g_ss[i0 + t];

    int tx = t & 31, ty = t >> 5;  // cols tx*3..+2, rows ty*4..+3
    float acc[4][3] = {};

    for (int j0 = jbase; j0 < jbase + 512; j0 += 16) {
        __syncthreads();
        if (t < 16) st_sh[t] = g_st[j0 + t];
#pragma unroll
        for (int i = 0; i < 6; i++) {
            int lin = t + i * 256;
            int k = lin / 96, c = lin % 96;
            W1t[k][c] = W1[(size_t)(j0 + k) * H1 + c];
        }
        __syncthreads();
#pragma unroll
        for (int e = 0; e < 2; e++) {
            int lin = t + e * 256;
            int i = lin >> 4, jj = lin & 15;
            float nas = ss_sh[i] + st_sh[jj];
            nas = nas > 0.f ? nas : 0.f;
            float m = nas * sw[(size_t)(i0 + i) * NN + j0 + jj];
            mt[i][jj] = m;
            msw_out[(size_t)(i0 + i) * NN + j0 + jj] = m;
        }
        __syncthreads();
#pragma unroll
        for (int k = 0; k < 16; k++) {
            float mr[4];
#pragma unroll
            for (int r = 0; r < 4; r++) mr[r] = mt[ty * 4 + r][k];
            float wv[3];
#pragma unroll
            for (int c = 0; c < 3; c++) wv[c] = W1t[k][tx * 3 + c];
#pragma unroll
            for (int r = 0; r < 4; r++)
#pragma unroll
                for (int c = 0; c < 3; c++) acc[r][c] = fmaf(mr[r], wv[c], acc[r][c]);
        }
    }
#pragma unroll
    for (int r = 0; r < 4; r++)
#pragma unroll
        for (int c = 0; c < 3; c++)
            atomicAdd(&g_h1[(size_t)(i0 + ty * 4 + r) * H1 + tx * 3 + c], acc[r][c]);
}

// ---------------- regression head: h1 -> h2 -> beta, y_hat ----------------
__global__ void __launch_bounds__(256) head_kernel(const float* __restrict__ W2,
                                                   const float* __restrict__ b2,
                                                   const float* __restrict__ W3,
                                                   const float* __restrict__ b3,
                                                   const float* __restrict__ ols,
                                                   const float* __restrict__ vx,
                                                   const float* __restrict__ b1v,
                                                   float* __restrict__ beta_out,
                                                   float* __restrict__ yhat_out) {
    __shared__ float W2s[96][32];
    __shared__ float W3s[32][16];
    __shared__ float b2s[32], b3s[16], olss[16], b1s[96];
    int t = threadIdx.x;
    for (int i = t; i < 96 * 32; i += 256) W2s[i / 32][i % 32] = W2[i];
    for (int i = t; i < 32 * 16; i += 256) W3s[i / 16][i % 16] = W3[i];
    if (t < 32) b2s[t] = b2[t];
    if (t < 16) { b3s[t] = b3[t]; olss[t] = ols[t]; }
    if (t < 96) b1s[t] = b1v[t];
    __syncthreads();

    int n = blockIdx.x * 256 + t;
    if (n >= NN) return;

    float h2[32];
#pragma unroll
    for (int c2 = 0; c2 < 32; c2++) h2[c2] = b2s[c2];
    for (int c = 0; c < 96; c++) {
        float hv = g_h1[(size_t)n * 96 + c] + b1s[c];
#pragma unroll
        for (int c2 = 0; c2 < 32; c2++) h2[c2] = fmaf(hv, W2s[c][c2], h2[c2]);
    }
    float yh = 0.f;
#pragma unroll
    for (int v = 0; v < 16; v++) {
        float s = b3s[v];
#pragma unroll
        for (int c2 = 0; c2 < 32; c2++) s = fmaf(h2[c2], W3s[c2][v], s);
        s = (s > 0.f) ? s : 0.2f * s;
        s *= olss[v];
        beta_out[(size_t)n * 16 + v] = s;
        yh = fmaf(s, vx[(size_t)n * 16 + v], yh);
    }
    yhat_out[n] = yh;
}

// ---------------- launcher (kernel launches ONLY — graph-capture safe) --------
extern "C" void kernel_launch(void* const* d_in, const int* in_sizes, int n_in,
                              void* d_out, int out_size) {
    const float* x    = (const float*)d_in[0];
    // d_in[1] = edge_distances (unused by reference)
    const float* sw   = (const float*)d_in[2];
    const float* Wp1  = (const float*)d_in[3];
    const float* a_s1 = (const float*)d_in[4];
    const float* a_t1 = (const float*)d_in[5];
    const float* Wsk  = (const float*)d_in[6];
    const float* bias1= (const float*)d_in[7];
    const float* Wp2  = (const float*)d_in[8];
    const float* a_s2 = (const float*)d_in[9];
    const float* a_t2 = (const float*)d_in[10];
    const float* W1   = (const float*)d_in[11];
    const float* b1   = (const float*)d_in[12];
    const float* W2   = (const float*)d_in[13];
    const float* b2   = (const float*)d_in[14];
    const float* W3   = (const float*)d_in[15];
    const float* b3   = (const float*)d_in[16];
    const float* ols  = (const float*)d_in[17];
    const float* vx   = (const float*)d_in[18];

    float* out = (float*)d_out;
    float* beta_out = out;                       // N*V = 65536
    float* yhat_out = out + NN * VV;             // N = 4096
    float* msw_out  = out + NN * VV + NN;        // N*N

    zero_h1<<<(NN * H1 + 255) / 256, 256>>>();
    xgemm_dual<<<dim3(D2 / 64, NN / 64), 256>>>(x, Wp1, Wsk);
    node_scores<<<(NN * HH + 255) / 256, 256>>>(a_s1, a_t1);
    attn_kernel<<<NN / 32, 256>>>(sw, bias1);
    p2gemm<<<dim3(D2 / 64, NN / 64), 256>>>(Wp2);
    gatw_scores<<<NN / 256, 256>>>(a_s2, a_t2);
    msw_h1<<<dim3(8, NN / 32), 256>>>(sw, W1, msw_out);
    head_kernel<<<NN / 256, 256>>>(W2, b2, W3, b3, ols, vx, b1, beta_out, yhat_out);
}

// round 9
// speedup vs baseline: 1.2210x; 1.2210x over previous
#include <cuda_runtime.h>
#include <math.h>

#define NN 4096
#define F_IN 128
#define HH 4
#define FO 64
#define D2 256
#define VV 16
#define H1 96
#define H2 32
#define JSPLIT 4
#define JLEN (NN / JSPLIT)

// ---------------- scratch (device globals; no allocs allowed) ----------------
__device__ float g_p[NN * D2];       // x @ Wp1
__device__ float g_skip[NN * D2];    // x @ Wskip1
__device__ float g_out1[NN * D2];    // elu(attn-out + skip + bias1)
__device__ float g_p2[NN * D2];      // out1 @ Wp2
__device__ float g_num[NN * D2];     // attention numerator (split-K accum)
__device__ float g_Z[HH * NN];       // softmax denominators (split-K accum)
__device__ float g_ssrc[HH * NN];
__device__ float g_stgt[HH * NN];
__device__ float g_E1s[HH * NN];
__device__ float g_E2s[HH * NN];
__device__ float g_E1t[HH * NN];
__device__ float g_E2t[HH * NN];
__device__ float g_ss[NN];
__device__ float g_st[NN];
__device__ float g_h1[NN * H1];      // msw @ W1 (accumulated via atomics)

// ---------------- zero accumulators ----------------
__global__ void zero_acc() {
    int t = blockIdx.x * blockDim.x + threadIdx.x;
    if (t < NN * D2) g_num[t] = 0.f;
    if (t < HH * NN) g_Z[t] = 0.f;
    if (t < NN * H1) g_h1[t] = 0.f;
}

// ---------------- fused dual SGEMM: g_p = x@Wp1, g_skip = x@Wsk ----------------
__global__ void __launch_bounds__(256) xgemm_dual(const float* __restrict__ x,
                                                  const float* __restrict__ Wp1,
                                                  const float* __restrict__ Wsk) {
    __shared__ float As[16][64];
    __shared__ float B1s[16][64];
    __shared__ float B2s[16][64];
    int t = threadIdx.x;
    int tx = t & 15, ty = t >> 4;
    int m0 = blockIdx.y * 64, n0 = blockIdx.x * 64;
    float acc1[4][4] = {};
    float acc2[4][4] = {};
    for (int k0 = 0; k0 < F_IN; k0 += 16) {
#pragma unroll
        for (int i = 0; i < 4; i++) {
            int lin = t + i * 256;
            int m = lin >> 4, k = lin & 15;
            As[k][m] = x[(size_t)(m0 + m) * F_IN + k0 + k];
        }
#pragma unroll
        for (int i = 0; i < 4; i++) {
            int lin = t + i * 256;
            int k = lin >> 6, n = lin & 63;
            B1s[k][n] = Wp1[(size_t)(k0 + k) * D2 + n0 + n];
            B2s[k][n] = Wsk[(size_t)(k0 + k) * D2 + n0 + n];
        }
        __syncthreads();
#pragma unroll
        for (int k = 0; k < 16; k++) {
            float a[4], b1[4], b2[4];
#pragma unroll
            for (int r = 0; r < 4; r++) a[r] = As[k][ty * 4 + r];
#pragma unroll
            for (int c = 0; c < 4; c++) { b1[c] = B1s[k][tx * 4 + c]; b2[c] = B2s[k][tx * 4 + c]; }
#pragma unroll
            for (int r = 0; r < 4; r++)
#pragma unroll
                for (int c = 0; c < 4; c++) {
                    acc1[r][c] = fmaf(a[r], b1[c], acc1[r][c]);
                    acc2[r][c] = fmaf(a[r], b2[c], acc2[r][c]);
                }
        }
        __syncthreads();
    }
#pragma unroll
    for (int r = 0; r < 4; r++)
#pragma unroll
        for (int c = 0; c < 4; c++) {
            size_t idx = (size_t)(m0 + ty * 4 + r) * D2 + n0 + tx * 4 + c;
            g_p[idx] = acc1[r][c];
            g_skip[idx] = acc2[r][c];
        }
}

// ---------------- SGEMM: g_p2 = g_out1 @ Wp2 (4096x256 @ 256x256) ----------------
__global__ void __launch_bounds__(256) p2gemm(const float* __restrict__ Wp2) {
    __shared__ float As[16][64];
    __shared__ float Bs[16][64];
    int t = threadIdx.x;
    int tx = t & 15, ty = t >> 4;
    int m0 = blockIdx.y * 64, n0 = blockIdx.x * 64;
    float acc[4][4] = {};
    for (int k0 = 0; k0 < D2; k0 += 16) {
#pragma unroll
        for (int i = 0; i < 4; i++) {
            int lin = t + i * 256;
            int m = lin >> 4, k = lin & 15;
            As[k][m] = g_out1[(size_t)(m0 + m) * D2 + k0 + k];
        }
#pragma unroll
        for (int i = 0; i < 4; i++) {
            int lin = t + i * 256;
            int k = lin >> 6, n = lin & 63;
            Bs[k][n] = Wp2[(size_t)(k0 + k) * D2 + n0 + n];
        }
        __syncthreads();
#pragma unroll
        for (int k = 0; k < 16; k++) {
            float a[4], b[4];
#pragma unroll
            for (int r = 0; r < 4; r++) a[r] = As[k][ty * 4 + r];
#pragma unroll
            for (int c = 0; c < 4; c++) b[c] = Bs[k][tx * 4 + c];
#pragma unroll
            for (int r = 0; r < 4; r++)
#pragma unroll
                for (int c = 0; c < 4; c++) acc[r][c] = fmaf(a[r], b[c], acc[r][c]);
        }
        __syncthreads();
    }
#pragma unroll
    for (int r = 0; r < 4; r++)
#pragma unroll
        for (int c = 0; c < 4; c++)
            g_p2[(size_t)(m0 + ty * 4 + r) * D2 + n0 + tx * 4 + c] = acc[r][c];
}

// ---------------- per-node GAT scores + exp factor tables ----------------
__global__ void node_scores(const float* __restrict__ a_src,
                            const float* __restrict__ a_tgt) {
    int t = blockIdx.x * blockDim.x + threadIdx.x;
    if (t >= NN * HH) return;
    int n = t >> 2, h = t & 3;
    const float* pr = g_p + (size_t)n * D2 + h * FO;
    float ss = 0.f, st = 0.f;
#pragma unroll 8
    for (int f = 0; f < FO; f++) {
        float pv = pr[f];
        ss = fmaf(pv, a_src[h * FO + f], ss);
        st = fmaf(pv, a_tgt[h * FO + f], st);
    }
    int idx = h * NN + n;
    g_ssrc[idx] = ss;
    g_stgt[idx] = st;
    g_E1s[idx] = expf(ss);
    g_E2s[idx] = expf(0.2f * ss);
    g_E1t[idx] = expf(st);
    g_E2t[idx] = expf(0.2f * st);
}

// ---------------- split-K fused GAT attention ----------------
// Partial numerator and Z over j-range [blockIdx.y*JLEN, +JLEN), atomics out.
// Block: 32 i-rows x 256 cols, 4 rows per warp; j chunks of 16.
__global__ void __launch_bounds__(256) attn_split(const float* __restrict__ sw) {
    __shared__ float Psh[16][256];
    __shared__ float Wt[32][16][4];                  // [i][j][h]
    __shared__ float ss_sh[4][32], E1s_sh[4][32], E2s_sh[4][32];
    __shared__ float st_sh[4][16], E1t_sh[4][16], E2t_sh[4][16];
    __shared__ float Zsh[32][4];

    int t = threadIdx.x;
    int i0 = blockIdx.x * 32;
    int jbase = blockIdx.y * JLEN;

    if (t < 128) {
        int h = t >> 5, i = t & 31;
        int idx = h * NN + i0 + i;
        ss_sh[h][i] = g_ssrc[idx];
        E1s_sh[h][i] = g_E1s[idx];
        E2s_sh[h][i] = g_E2s[idx];
        Zsh[i][h] = 0.f;
    }

    int w = t >> 5, tx = t & 31;
    int r0 = w * 4;
    int head = tx >> 3;
    int c0 = tx * 8;

    float zpart[2][4] = {};
    float acc[4][8] = {};

    for (int j0 = jbase; j0 < jbase + JLEN; j0 += 16) {
        __syncthreads();
        if (t < 64) {
            int h = t >> 4, jj = t & 15;
            int idx = h * NN + j0 + jj;
            st_sh[h][jj] = g_stgt[idx];
            E1t_sh[h][jj] = g_E1t[idx];
            E2t_sh[h][jj] = g_E2t[idx];
        }
#pragma unroll
        for (int i = 0; i < 16; i++)
            Psh[i][t] = g_p[(size_t)(j0 + i) * D2 + t];
        __syncthreads();

        // weight-builder: 32x16 = 512 entries, 2 per thread
#pragma unroll
        for (int e = 0; e < 2; e++) {
            int lin = t + e * 256;
            int wi = lin >> 4, wj = lin & 15;
            float swv = sw[(size_t)(i0 + wi) * NN + j0 + wj];
            bool valid = swv > 0.f;
#pragma unroll
            for (int h = 0; h < 4; h++) {
                float tv = ss_sh[h][wi] + st_sh[h][wj];
                float wgt = 0.f;
                if (valid)
                    wgt = (tv > 0.f) ? E1s_sh[h][wi] * E1t_sh[h][wj]
                                     : E2s_sh[h][wi] * E2t_sh[h][wj];
                Wt[wi][wj][h] = wgt;
                zpart[e][h] += wgt;
            }
        }
        __syncthreads();

#pragma unroll
        for (int k = 0; k < 16; k++) {
            float wr[4];
#pragma unroll
            for (int r = 0; r < 4; r++) wr[r] = Wt[r0 + r][k][head];
            float4 pa = *(const float4*)&Psh[k][c0];
            float4 pb = *(const float4*)&Psh[k][c0 + 4];
            float pv[8] = {pa.x, pa.y, pa.z, pa.w, pb.x, pb.y, pb.z, pb.w};
#pragma unroll
            for (int r = 0; r < 4; r++)
#pragma unroll
                for (int c = 0; c < 8; c++)
                    acc[r][c] = fmaf(wr[r], pv[c], acc[r][c]);
        }
    }
    __syncthreads();
#pragma unroll
    for (int e = 0; e < 2; e++) {
        int wi = (t + e * 256) >> 4;
#pragma unroll
        for (int h = 0; h < 4; h++) atomicAdd(&Zsh[wi][h], zpart[e][h]);
    }
    __syncthreads();

    if (t < 128) {
        int h = t >> 5, i = t & 31;
        atomicAdd(&g_Z[h * NN + i0 + i], Zsh[i][h]);
    }
#pragma unroll
    for (int r = 0; r < 4; r++) {
        int gi = i0 + r0 + r;
#pragma unroll
        for (int c = 0; c < 8; c++)
            atomicAdd(&g_num[(size_t)gi * D2 + c0 + c], acc[r][c]);
    }
}

// ---------------- finalize: out1 = elu(num/Z + skip + bias1) ----------------
__global__ void attn_finalize(const float* __restrict__ bias1) {
    int t = blockIdx.x * blockDim.x + threadIdx.x;
    if (t >= NN * D2) return;
    int i = t >> 8, c = t & 255;
    int h = c >> 6;
    float v = g_num[t] / g_Z[h * NN + i] + g_skip[t] + bias1[c];
    g_out1[t] = (v > 0.f) ? v : expm1f(v);
}

// ---------------- GATW scores ----------------
__global__ void gatw_scores(const float* __restrict__ a_src2,
                            const float* __restrict__ a_tgt2) {
    int n = blockIdx.x * blockDim.x + threadIdx.x;
    if (n >= NN) return;
    float ss = 0.f, st = 0.f;
    const float* row = g_p2 + (size_t)n * D2;
#pragma unroll 8
    for (int c = 0; c < D2; c++) {
        float v = row[c];
        ss = fmaf(v, a_src2[c], ss);
        st = fmaf(v, a_tgt2[c], st);
    }
    g_ss[n] = ss;
    g_st[n] = st;
}

// ---------------- fused msw + (msw @ W1) with split-K atomics ----------------
__global__ void __launch_bounds__(256) msw_h1(const float* __restrict__ sw,
                                              const float* __restrict__ W1,
                                              float* __restrict__ msw_out) {
    __shared__ float ss_sh[32];
    __shared__ float st_sh[16];
    __shared__ float W1t[16][96];
    __shared__ float mt[32][16];

    int t = threadIdx.x;
    int i0 = blockIdx.y * 32;
    int jbase = blockIdx.x * 512;
    if (t < 32) ss_sh[t] = g_ss[i0 + t];

    int tx = t & 31, ty = t >> 5;
    float acc[4][3] = {};

    for (int j0 = jbase; j0 < jbase + 512; j0 += 16) {
        __syncthreads();
        if (t < 16) st_sh[t] = g_st[j0 + t];
#pragma unroll
        for (int i = 0; i < 6; i++) {
            int lin = t + i * 256;
            int k = lin / 96, c = lin % 96;
            W1t[k][c] = W1[(size_t)(j0 + k) * H1 + c];
        }
        __syncthreads();
#pragma unroll
        for (int e = 0; e < 2; e++) {
            int lin = t + e * 256;
            int i = lin >> 4, jj = lin & 15;
            float nas = ss_sh[i] + st_sh[jj];
            nas = nas > 0.f ? nas : 0.f;
            float m = nas * sw[(size_t)(i0 + i) * NN + j0 + jj];
            mt[i][jj] = m;
            msw_out[(size_t)(i0 + i) * NN + j0 + jj] = m;
        }
        __syncthreads();
#pragma unroll
        for (int k = 0; k < 16; k++) {
            float mr[4];
#pragma unroll
            for (int r = 0; r < 4; r++) mr[r] = mt[ty * 4 + r][k];
            float wv[3];
#pragma unroll
            for (int c = 0; c < 3; c++) wv[c] = W1t[k][tx * 3 + c];
#pragma unroll
            for (int r = 0; r < 4; r++)
#pragma unroll
                for (int c = 0; c < 3; c++) acc[r][c] = fmaf(mr[r], wv[c], acc[r][c]);
        }
    }
#pragma unroll
    for (int r = 0; r < 4; r++)
#pragma unroll
        for (int c = 0; c < 3; c++)
            atomicAdd(&g_h1[(size_t)(i0 + ty * 4 + r) * H1 + tx * 3 + c], acc[r][c]);
}

// ---------------- regression head: h1 -> h2 -> beta, y_hat ----------------
__global__ void __launch_bounds__(256) head_kernel(const float* __restrict__ W2,
                                                   const float* __restrict__ b2,
                                                   const float* __restrict__ W3,
                                                   const float* __restrict__ b3,
                                                   const float* __restrict__ ols,
                                                   const float* __restrict__ vx,
                                                   const float* __restrict__ b1v,
                                                   float* __restrict__ beta_out,
                                                   float* __restrict__ yhat_out) {
    __shared__ float W2s[96][32];
    __shared__ float W3s[32][16];
    __shared__ float b2s[32], b3s[16], olss[16], b1s[96];
    int t = threadIdx.x;
    for (int i = t; i < 96 * 32; i += 256) W2s[i / 32][i % 32] = W2[i];
    for (int i = t; i < 32 * 16; i += 256) W3s[i / 16][i % 16] = W3[i];
    if (t < 32) b2s[t] = b2[t];
    if (t < 16) { b3s[t] = b3[t]; olss[t] = ols[t]; }
    if (t < 96) b1s[t] = b1v[t];
    __syncthreads();

    int n = blockIdx.x * 256 + t;
    if (n >= NN) return;

    float h2[32];
#pragma unroll
    for (int c2 = 0; c2 < 32; c2++) h2[c2] = b2s[c2];
    for (int c = 0; c < 96; c++) {
        float hv = g_h1[(size_t)n * 96 + c] + b1s[c];
#pragma unroll
        for (int c2 = 0; c2 < 32; c2++) h2[c2] = fmaf(hv, W2s[c][c2], h2[c2]);
    }
    float yh = 0.f;
#pragma unroll
    for (int v = 0; v < 16; v++) {
        float s = b3s[v];
#pragma unroll
        for (int c2 = 0; c2 < 32; c2++) s = fmaf(h2[c2], W3s[c2][v], s);
        s = (s > 0.f) ? s : 0.2f * s;
        s *= olss[v];
        beta_out[(size_t)n * 16 + v] = s;
        yh = fmaf(s, vx[(size_t)n * 16 + v], yh);
    }
    yhat_out[n] = yh;
}

// ---------------- launcher (kernel launches ONLY — graph-capture safe) --------
extern "C" void kernel_launch(void* const* d_in, const int* in_sizes, int n_in,
                              void* d_out, int out_size) {
    const float* x    = (const float*)d_in[0];
    const float* sw   = (const float*)d_in[2];
    const float* Wp1  = (const float*)d_in[3];
    const float* a_s1 = (const float*)d_in[4];
    const float* a_t1 = (const float*)d_in[5];
    const float* Wsk  = (const float*)d_in[6];
    const float* bias1= (const float*)d_in[7];
    const float* Wp2  = (const float*)d_in[8];
    const float* a_s2 = (const float*)d_in[9];
    const float* a_t2 = (const float*)d_in[10];
    const float* W1   = (const float*)d_in[11];
    const float* b1   = (const float*)d_in[12];
    const float* W2   = (const float*)d_in[13];
    const float* b2   = (const float*)d_in[14];
    const float* W3   = (const float*)d_in[15];
    const float* b3   = (const float*)d_in[16];
    const float* ols  = (const float*)d_in[17];
    const float* vx   = (const float*)d_in[18];

    float* out = (float*)d_out;
    float* beta_out = out;                       // N*V = 65536
    float* yhat_out = out + NN * VV;             // N = 4096
    float* msw_out  = out + NN * VV + NN;        // N*N

    zero_acc<<<(NN * D2 + 255) / 256, 256>>>();
    xgemm_dual<<<dim3(D2 / 64, NN / 64), 256>>>(x, Wp1, Wsk);
    node_scores<<<(NN * HH + 255) / 256, 256>>>(a_s1, a_t1);
    attn_split<<<dim3(NN / 32, JSPLIT), 256>>>(sw);
    attn_finalize<<<(NN * D2 + 255) / 256, 256>>>(bias1);
    p2gemm<<<dim3(D2 / 64, NN / 64), 256>>>(Wp2);
    gatw_scores<<<NN / 256, 256>>>(a_s2, a_t2);
    msw_h1<<<dim3(8, NN / 32), 256>>>(sw, W1, msw_out);
    head_kernel<<<NN / 256, 256>>>(W2, b2, W3, b3, ols, vx, b1, beta_out, yhat_out);
}

// round 10
// speedup vs baseline: 1.9745x; 1.6171x over previous
#include <cuda_runtime.h>
#include <math.h>

#define NN 4096
#define F_IN 128
#define HH 4
#define FO 64
#define D2 256
#define VV 16
#define H1 96
#define H2 32
#define JSPLIT 8
#define JLEN (NN / JSPLIT)

// ---------------- scratch (device globals; no allocs allowed) ----------------
__device__ __align__(16) float g_p[NN * D2];       // x @ Wp1
__device__ __align__(16) float g_skip[NN * D2];    // x @ Wskip1
__device__ __align__(16) float g_out1[NN * D2];    // elu(attn-out + skip + bias1)
__device__ __align__(16) float g_p2[NN * D2];      // out1 @ Wp2
__device__ __align__(16) float g_num[NN * D2];     // attention numerator (split-K accum)
__device__ float g_Z[HH * NN];                     // softmax denominators (split-K accum)
__device__ float g_ssrc[HH * NN];
__device__ __align__(16) float g_stgt[HH * NN];
__device__ float g_E1s[HH * NN];
__device__ float g_E2s[HH * NN];
__device__ __align__(16) float g_E1t[HH * NN];
__device__ __align__(16) float g_E2t[HH * NN];
__device__ float g_ss[NN];
__device__ float g_st[NN];
__device__ float g_h1[NN * H1];                    // msw @ W1 (atomic accum)

// ---------------- zero accumulators ----------------
__global__ void zero_acc() {
    int t = blockIdx.x * blockDim.x + threadIdx.x;
    if (t < NN * D2) g_num[t] = 0.f;
    if (t < HH * NN) g_Z[t] = 0.f;
    if (t < NN * H1) g_h1[t] = 0.f;
}

// ---------------- fused dual SGEMM: g_p = x@Wp1, g_skip = x@Wsk ----------------
__global__ void __launch_bounds__(256) xgemm_dual(const float* __restrict__ x,
                                                  const float* __restrict__ Wp1,
                                                  const float* __restrict__ Wsk) {
    __shared__ float As[16][64];
    __shared__ float B1s[16][64];
    __shared__ float B2s[16][64];
    int t = threadIdx.x;
    int tx = t & 15, ty = t >> 4;
    int m0 = blockIdx.y * 64, n0 = blockIdx.x * 64;
    float acc1[4][4] = {};
    float acc2[4][4] = {};
    for (int k0 = 0; k0 < F_IN; k0 += 16) {
#pragma unroll
        for (int i = 0; i < 4; i++) {
            int lin = t + i * 256;
            int m = lin >> 4, k = lin & 15;
            As[k][m] = x[(size_t)(m0 + m) * F_IN + k0 + k];
        }
#pragma unroll
        for (int i = 0; i < 4; i++) {
            int lin = t + i * 256;
            int k = lin >> 6, n = lin & 63;
            B1s[k][n] = Wp1[(size_t)(k0 + k) * D2 + n0 + n];
            B2s[k][n] = Wsk[(size_t)(k0 + k) * D2 + n0 + n];
        }
        __syncthreads();
#pragma unroll
        for (int k = 0; k < 16; k++) {
            float a[4], b1[4], b2[4];
#pragma unroll
            for (int r = 0; r < 4; r++) a[r] = As[k][ty * 4 + r];
#pragma unroll
            for (int c = 0; c < 4; c++) { b1[c] = B1s[k][tx * 4 + c]; b2[c] = B2s[k][tx * 4 + c]; }
#pragma unroll
            for (int r = 0; r < 4; r++)
#pragma unroll
                for (int c = 0; c < 4; c++) {
                    acc1[r][c] = fmaf(a[r], b1[c], acc1[r][c]);
                    acc2[r][c] = fmaf(a[r], b2[c], acc2[r][c]);
                }
        }
        __syncthreads();
    }
#pragma unroll
    for (int r = 0; r < 4; r++)
#pragma unroll
        for (int c = 0; c < 4; c++) {
            size_t idx = (size_t)(m0 + ty * 4 + r) * D2 + n0 + tx * 4 + c;
            g_p[idx] = acc1[r][c];
            g_skip[idx] = acc2[r][c];
        }
}

// ---------------- SGEMM: g_p2 = g_out1 @ Wp2 (4096x256 @ 256x256) ----------------
__global__ void __launch_bounds__(256) p2gemm(const float* __restrict__ Wp2) {
    __shared__ float As[16][64];
    __shared__ float Bs[16][64];
    int t = threadIdx.x;
    int tx = t & 15, ty = t >> 4;
    int m0 = blockIdx.y * 64, n0 = blockIdx.x * 64;
    float acc[4][4] = {};
    for (int k0 = 0; k0 < D2; k0 += 16) {
#pragma unroll
        for (int i = 0; i < 4; i++) {
            int lin = t + i * 256;
            int m = lin >> 4, k = lin & 15;
            As[k][m] = g_out1[(size_t)(m0 + m) * D2 + k0 + k];
        }
#pragma unroll
        for (int i = 0; i < 4; i++) {
            int lin = t + i * 256;
            int k = lin >> 6, n = lin & 63;
            Bs[k][n] = Wp2[(size_t)(k0 + k) * D2 + n0 + n];
        }
        __syncthreads();
#pragma unroll
        for (int k = 0; k < 16; k++) {
            float a[4], b[4];
#pragma unroll
            for (int r = 0; r < 4; r++) a[r] = As[k][ty * 4 + r];
#pragma unroll
            for (int c = 0; c < 4; c++) b[c] = Bs[k][tx * 4 + c];
#pragma unroll
            for (int r = 0; r < 4; r++)
#pragma unroll
                for (int c = 0; c < 4; c++) acc[r][c] = fmaf(a[r], b[c], acc[r][c]);
        }
        __syncthreads();
    }
#pragma unroll
    for (int r = 0; r < 4; r++)
#pragma unroll
        for (int c = 0; c < 4; c++)
            g_p2[(size_t)(m0 + ty * 4 + r) * D2 + n0 + tx * 4 + c] = acc[r][c];
}

// ---------------- per-node GAT scores + exp factor tables ----------------
__global__ void node_scores(const float* __restrict__ a_src,
                            const float* __restrict__ a_tgt) {
    int t = blockIdx.x * blockDim.x + threadIdx.x;
    if (t >= NN * HH) return;
    int n = t >> 2, h = t & 3;
    const float* pr = g_p + (size_t)n * D2 + h * FO;
    float ss = 0.f, st = 0.f;
#pragma unroll 8
    for (int f = 0; f < FO; f++) {
        float pv = pr[f];
        ss = fmaf(pv, a_src[h * FO + f], ss);
        st = fmaf(pv, a_tgt[h * FO + f], st);
    }
    int idx = h * NN + n;
    g_ssrc[idx] = ss;
    g_stgt[idx] = st;
    g_E1s[idx] = expf(ss);
    g_E2s[idx] = expf(0.2f * ss);
    g_E1t[idx] = expf(st);
    g_E2t[idx] = expf(0.2f * st);
}

// ---------------- split-K fused GAT attention (conflict-free v2) ----------------
// Block: 32 i-rows x 256 cols; j-tiles of 32; 2 barriers per tile.
// Lane owns cols [lane*4, +4) (head lane>>4) and [128+lane*4, +4) (head +2).
__global__ void __launch_bounds__(256) attn_split(const float* __restrict__ sw) {
    __shared__ __align__(16) float Psh[32][256];     // 32 KB
    __shared__ __align__(16) float Wts[4 * 1032];    // head planes, stride 1032 (bank-staggered)
    __shared__ float ss_sh[4][32], E1s_sh[4][32], E2s_sh[4][32];
    __shared__ float Zsh[32][4];

    int t = threadIdx.x;
    int i0 = blockIdx.x * 32;
    int jbase = blockIdx.y * JLEN;

    if (t < 128) {
        int h = t >> 5, i = t & 31;
        int idx = h * NN + i0 + i;
        ss_sh[h][i] = g_ssrc[idx];
        E1s_sh[h][i] = g_E1s[idx];
        E2s_sh[h][i] = g_E2s[idx];
        Zsh[i][h] = 0.f;
    }

    int w = t >> 5, lane = t & 31;
    int r0 = w * 4;            // 4 i-rows per warp
    int hA = lane >> 4;        // head for cols [cA, cA+4)
    int hB = hA + 2;           // head for cols [128+cA, ...)
    int cA = lane * 4;         // 0..124
    int wi = t >> 3;           // builder: i-row 0..31
    int jj4 = (t & 7) * 4;     // builder: j offset 0..28
    int prow = t >> 6;         // P loader
    int pcol = (t & 63) * 4;

    float zpart[4] = {0.f, 0.f, 0.f, 0.f};
    float accA[4][4] = {};
    float accB[4][4] = {};

    for (int j0 = jbase; j0 < jbase + JLEN; j0 += 32) {
        __syncthreads();   // prev-tile FMA done; also orders prologue on iter 0

        // load P tile (conflict-free float4)
#pragma unroll
        for (int rr = 0; rr < 8; rr++) {
            int row = rr * 4 + prow;
            *(float4*)&Psh[row][pcol] =
                *(const float4*)&g_p[(size_t)(j0 + row) * D2 + pcol];
        }

        // build weight tile: w[h][i][j] (tables read from gmem — L1/L2 hot)
        {
            float4 swv = *(const float4*)&sw[(size_t)(i0 + wi) * NN + j0 + jj4];
#pragma unroll
            for (int h = 0; h < 4; h++) {
                float ssi = ss_sh[h][wi];
                float e1s = E1s_sh[h][wi];
                float e2s = E2s_sh[h][wi];
                int gj = h * NN + j0 + jj4;
                float4 stv = *(const float4*)&g_stgt[gj];
                float4 e1t = *(const float4*)&g_E1t[gj];
                float4 e2t = *(const float4*)&g_E2t[gj];
                float4 wv;
                wv.x = (swv.x > 0.f) ? ((ssi + stv.x > 0.f) ? e1s * e1t.x : e2s * e2t.x) : 0.f;
                wv.y = (swv.y > 0.f) ? ((ssi + stv.y > 0.f) ? e1s * e1t.y : e2s * e2t.y) : 0.f;
                wv.z = (swv.z > 0.f) ? ((ssi + stv.z > 0.f) ? e1s * e1t.z : e2s * e2t.z) : 0.f;
                wv.w = (swv.w > 0.f) ? ((ssi + stv.w > 0.f) ? e1s * e1t.w : e2s * e2t.w) : 0.f;
                zpart[h] += (wv.x + wv.y) + (wv.z + wv.w);
                *(float4*)&Wts[h * 1032 + wi * 32 + jj4] = wv;
            }
        }
        __syncthreads();

        // FMA over the 32-j tile
#pragma unroll
        for (int k = 0; k < 32; k += 4) {
            // half A: head hA, cols cA..cA+3
            {
                float wq[4][4];
#pragma unroll
                for (int r = 0; r < 4; r++) {
                    float4 tq = *(const float4*)&Wts[hA * 1032 + (r0 + r) * 32 + k];
                    wq[r][0] = tq.x; wq[r][1] = tq.y; wq[r][2] = tq.z; wq[r][3] = tq.w;
                }
#pragma unroll
                for (int kk = 0; kk < 4; kk++) {
                    float4 pa = *(const float4*)&Psh[k + kk][cA];
#pragma unroll
                    for (int r = 0; r < 4; r++) {
                        accA[r][0] = fmaf(wq[r][kk], pa.x, accA[r][0]);
                        accA[r][1] = fmaf(wq[r][kk], pa.y, accA[r][1]);
                        accA[r][2] = fmaf(wq[r][kk], pa.z, accA[r][2]);
                        accA[r][3] = fmaf(wq[r][kk], pa.w, accA[r][3]);
                    }
                }
            }
            // half B: head hB, cols 128+cA..+3
            {
                float wq[4][4];
#pragma unroll
                for (int r = 0; r < 4; r++) {
                    float4 tq = *(const float4*)&Wts[hB * 1032 + (r0 + r) * 32 + k];
                    wq[r][0] = tq.x; wq[r][1] = tq.y; wq[r][2] = tq.z; wq[r][3] = tq.w;
                }
#pragma unroll
                for (int kk = 0; kk < 4; kk++) {
                    float4 pb = *(const float4*)&Psh[k + kk][128 + cA];
#pragma unroll
                    for (int r = 0; r < 4; r++) {
                        accB[r][0] = fmaf(wq[r][kk], pb.x, accB[r][0]);
                        accB[r][1] = fmaf(wq[r][kk], pb.y, accB[r][1]);
                        accB[r][2] = fmaf(wq[r][kk], pb.z, accB[r][2]);
                        accB[r][3] = fmaf(wq[r][kk], pb.w, accB[r][3]);
                    }
                }
            }
        }
    }
    __syncthreads();

    // Z reduction: thread owns (wi, all h) partials over its j-slice
#pragma unroll
    for (int h = 0; h < 4; h++) atomicAdd(&Zsh[wi][h], zpart[h]);
    __syncthreads();
    if (t < 128) {
        int h = t >> 5, i = t & 31;
        atomicAdd(&g_Z[h * NN + i0 + i], Zsh[i][h]);
    }
#pragma unroll
    for (int r = 0; r < 4; r++) {
        size_t base = (size_t)(i0 + r0 + r) * D2;
#pragma unroll
        for (int c = 0; c < 4; c++) {
            atomicAdd(&g_num[base + cA + c], accA[r][c]);
            atomicAdd(&g_num[base + 128 + cA + c], accB[r][c]);
        }
    }
}

// ---------------- finalize: out1 = elu(num/Z + skip + bias1) ----------------
__global__ void attn_finalize(const float* __restrict__ bias1) {
    int t = blockIdx.x * blockDim.x + threadIdx.x;
    if (t >= NN * D2) return;
    int i = t >> 8, c = t & 255;
    int h = c >> 6;
    float v = g_num[t] / g_Z[h * NN + i] + g_skip[t] + bias1[c];
    g_out1[t] = (v > 0.f) ? v : expm1f(v);
}

// ---------------- GATW scores ----------------
__global__ void gatw_scores(const float* __restrict__ a_src2,
                            const float* __restrict__ a_tgt2) {
    int n = blockIdx.x * blockDim.x + threadIdx.x;
    if (n >= NN) return;
    float ss = 0.f, st = 0.f;
    const float* row = g_p2 + (size_t)n * D2;
#pragma unroll 8
    for (int c = 0; c < D2; c++) {
        float v = row[c];
        ss = fmaf(v, a_src2[c], ss);
        st = fmaf(v, a_tgt2[c], st);
    }
    g_ss[n] = ss;
    g_st[n] = st;
}

// ---------------- fused msw + (msw @ W1) with split-K atomics ----------------
__global__ void __launch_bounds__(256) msw_h1(const float* __restrict__ sw,
                                              const float* __restrict__ W1,
                                              float* __restrict__ msw_out) {
    __shared__ float ss_sh[32];
    __shared__ float st_sh[16];
    __shared__ float W1t[16][96];
    __shared__ float mt[32][16];

    int t = threadIdx.x;
    int i0 = blockIdx.y * 32;
    int jbase = blockIdx.x * 512;
    if (t < 32) ss_sh[t] = g_ss[i0 + t];

    int tx = t & 31, ty = t >> 5;
    float acc[4][3] = {};

    for (int j0 = jbase; j0 < jbase + 512; j0 += 16) {
        __syncthreads();
        if (t < 16) st_sh[t] = g_st[j0 + t];
#pragma unroll
        for (int i = 0; i < 6; i++) {
            int lin = t + i * 256;
            int k = lin / 96, c = lin % 96;
            W1t[k][c] = W1[(size_t)(j0 + k) * H1 + c];
        }
        __syncthreads();
#pragma unroll
        for (int e = 0; e < 2; e++) {
            int lin = t + e * 256;
            int i = lin >> 4, jj = lin & 15;
            float nas = ss_sh[i] + st_sh[jj];
            nas = nas > 0.f ? nas : 0.f;
            float m = nas * sw[(size_t)(i0 + i) * NN + j0 + jj];
            mt[i][jj] = m;
            msw_out[(size_t)(i0 + i) * NN + j0 + jj] = m;
        }
        __syncthreads();
#pragma unroll
        for (int k = 0; k < 16; k++) {
            float mr[4];
#pragma unroll
            for (int r = 0; r < 4; r++) mr[r] = mt[ty * 4 + r][k];
            float wv[3];
#pragma unroll
            for (int c = 0; c < 3; c++) wv[c] = W1t[k][tx * 3 + c];
#pragma unroll
            for (int r = 0; r < 4; r++)
#pragma unroll
                for (int c = 0; c < 3; c++) acc[r][c] = fmaf(mr[r], wv[c], acc[r][c]);
        }
    }
#pragma unroll
    for (int r = 0; r < 4; r++)
#pragma unroll
        for (int c = 0; c < 3; c++)
            atomicAdd(&g_h1[(size_t)(i0 + ty * 4 + r) * H1 + tx * 3 + c], acc[r][c]);
}

// ---------------- regression head: h1 -> h2 -> beta, y_hat ----------------
__global__ void __launch_bounds__(256) head_kernel(const float* __restrict__ W2,
                                                   const float* __restrict__ b2,
                                                   const float* __restrict__ W3,
                                                   const float* __restrict__ b3,
                                                   const float* __restrict__ ols,
                                                   const float* __restrict__ vx,
                                                   const float* __restrict__ b1v,
                                                   float* __restrict__ beta_out,
                                                   float* __restrict__ yhat_out) {
    __shared__ float W2s[96][32];
    __shared__ float W3s[32][16];
    __shared__ float b2s[32], b3s[16], olss[16], b1s[96];
    int t = threadIdx.x;
    for (int i = t; i < 96 * 32; i += 256) W2s[i / 32][i % 32] = W2[i];
    for (int i = t; i < 32 * 16; i += 256) W3s[i / 16][i % 16] = W3[i];
    if (t < 32) b2s[t] = b2[t];
    if (t < 16) { b3s[t] = b3[t]; olss[t] = ols[t]; }
    if (t < 96) b1s[t] = b1v[t];
    __syncthreads();

    int n = blockIdx.x * 256 + t;
    if (n >= NN) return;

    float h2[32];
#pragma unroll
    for (int c2 = 0; c2 < 32; c2++) h2[c2] = b2s[c2];
    for (int c = 0; c < 96; c++) {
        float hv = g_h1[(size_t)n * 96 + c] + b1s[c];
#pragma unroll
        for (int c2 = 0; c2 < 32; c2++) h2[c2] = fmaf(hv, W2s[c][c2], h2[c2]);
    }
    float yh = 0.f;
#pragma unroll
    for (int v = 0; v < 16; v++) {
        float s = b3s[v];
#pragma unroll
        for (int c2 = 0; c2 < 32; c2++) s = fmaf(h2[c2], W3s[c2][v], s);
        s = (s > 0.f) ? s : 0.2f * s;
        s *= olss[v];
        beta_out[(size_t)n * 16 + v] = s;
        yh = fmaf(s, vx[(size_t)n * 16 + v], yh);
    }
    yhat_out[n] = yh;
}

// ---------------- launcher (kernel launches ONLY — graph-capture safe) --------
extern "C" void kernel_launch(void* const* d_in, const int* in_sizes, int n_in,
                              void* d_out, int out_size) {
    const float* x    = (const float*)d_in[0];
    const float* sw   = (const float*)d_in[2];
    const float* Wp1  = (const float*)d_in[3];
    const float* a_s1 = (const float*)d_in[4];
    const float* a_t1 = (const float*)d_in[5];
    const float* Wsk  = (const float*)d_in[6];
    const float* bias1= (const float*)d_in[7];
    const float* Wp2  = (const float*)d_in[8];
    const float* a_s2 = (const float*)d_in[9];
    const float* a_t2 = (const float*)d_in[10];
    const float* W1   = (const float*)d_in[11];
    const float* b1   = (const float*)d_in[12];
    const float* W2   = (const float*)d_in[13];
    const float* b2   = (const float*)d_in[14];
    const float* W3   = (const float*)d_in[15];
    const float* b3   = (const float*)d_in[16];
    const float* ols  = (const float*)d_in[17];
    const float* vx   = (const float*)d_in[18];

    float* out = (float*)d_out;
    float* beta_out = out;                       // N*V = 65536
    float* yhat_out = out + NN * VV;             // N = 4096
    float* msw_out  = out + NN * VV + NN;        // N*N

    zero_acc<<<(NN * D2 + 255) / 256, 256>>>();
    xgemm_dual<<<dim3(D2 / 64, NN / 64), 256>>>(x, Wp1, Wsk);
    node_scores<<<(NN * HH + 255) / 256, 256>>>(a_s1, a_t1);
    attn_split<<<dim3(NN / 32, JSPLIT), 256>>>(sw);
    attn_finalize<<<(NN * D2 + 255) / 256, 256>>>(bias1);
    p2gemm<<<dim3(D2 / 64, NN / 64), 256>>>(Wp2);
    gatw_scores<<<NN / 256, 256>>>(a_s2, a_t2);
    msw_h1<<<dim3(8, NN / 32), 256>>>(sw, W1, msw_out);
    head_kernel<<<NN / 256, 256>>>(W2, b2, W3, b3, ols, vx, b1, beta_out, yhat_out);
}